// round 1
// baseline (speedup 1.0000x reference)
#include <cuda_runtime.h>
#include <math.h>

#define NB 8
#define NC 512
#define NT 1024
#define NG 32
#define CPG 16          // channels per group
#define NH 8
#define HD 64

// Scratch (allocation-free rule: __device__ globals)
__device__ float g_xn[NB * NC * NT];        // 16 MB  GroupNorm output
__device__ float g_qkv[NB * 3 * NC * NT];   // 48 MB  QKV projection
__device__ float g_attn[NB * NC * NT];      // 16 MB  attention output

// ---------------------------------------------------------------------------
// GroupNorm(32, 512): one block per (b, group). 16 ch x 1024 = 16384 elems.
// ---------------------------------------------------------------------------
__global__ void groupnorm_kernel(const float* __restrict__ x,
                                 const float* __restrict__ nw,
                                 const float* __restrict__ nb) {
    int b = blockIdx.x >> 5;
    int g = blockIdx.x & 31;
    const float* xp = x + (size_t)(b * NC + g * CPG) * NT;
    float* op = g_xn + (size_t)(b * NC + g * CPG) * NT;
    int tid = threadIdx.x;

    float s = 0.f, sq = 0.f;
    const float4* xp4 = (const float4*)xp;
    const int N4 = CPG * NT / 4;  // 4096
    for (int i = tid; i < N4; i += 256) {
        float4 v = xp4[i];
        s  += v.x + v.y + v.z + v.w;
        sq += v.x * v.x + v.y * v.y + v.z * v.z + v.w * v.w;
    }
    __shared__ float rs[8], rq[8];
    #pragma unroll
    for (int off = 16; off; off >>= 1) {
        s  += __shfl_xor_sync(0xffffffffu, s, off);
        sq += __shfl_xor_sync(0xffffffffu, sq, off);
    }
    if ((tid & 31) == 0) { rs[tid >> 5] = s; rq[tid >> 5] = sq; }
    __syncthreads();
    if (tid < 32) {
        s  = (tid < 8) ? rs[tid] : 0.f;
        sq = (tid < 8) ? rq[tid] : 0.f;
        #pragma unroll
        for (int off = 4; off; off >>= 1) {
            s  += __shfl_xor_sync(0xffffffffu, s, off);
            sq += __shfl_xor_sync(0xffffffffu, sq, off);
        }
        if (tid == 0) { rs[0] = s; rq[0] = sq; }
    }
    __syncthreads();
    const float invn = 1.f / (CPG * NT);
    float mean = rs[0] * invn;
    float var = rq[0] * invn - mean * mean;
    float rinv = rsqrtf(var + 1e-5f);

    float4* op4 = (float4*)op;
    for (int i = tid; i < N4; i += 256) {
        int c = g * CPG + (i >> 8);   // 256 float4 per channel row
        float w = nw[c] * rinv;
        float bia = nb[c] - mean * w;
        float4 v = xp4[i];
        v.x = v.x * w + bia;
        v.y = v.y * w + bia;
        v.z = v.z * w + bia;
        v.w = v.w * w + bia;
        op4[i] = v;
    }
}

// ---------------------------------------------------------------------------
// Batched SGEMM: C[bz] = A (MxK, shared across batch) * B[bz] (KxN) + bias
// optionally + skip[bz].  128x128 tile, BK=8, 256 threads, 8x8 per thread.
// M % 128 == 0, N % 128 == 0, K % 8 == 0 (holds for all our shapes).
// ---------------------------------------------------------------------------
template <bool SKIP>
__global__ void sgemm128(const float* __restrict__ A, const float* __restrict__ Bm,
                         const float* __restrict__ bias, const float* __restrict__ skip,
                         float* __restrict__ Cm, int M, int N, int K) {
    int bz = blockIdx.z;
    const float* Bp = Bm + (size_t)bz * K * N;
    float* Cp = Cm + (size_t)bz * M * N;
    const float* Sp = SKIP ? (skip + (size_t)bz * M * N) : nullptr;
    int m0 = blockIdx.y * 128, n0 = blockIdx.x * 128;

    __shared__ float As[8][128];
    __shared__ float Bs[8][128];

    int tid = threadIdx.x;
    int tx = tid & 15, ty = tid >> 4;

    float acc[8][8];
    #pragma unroll
    for (int i = 0; i < 8; i++)
        #pragma unroll
        for (int j = 0; j < 8; j++) acc[i][j] = 0.f;

    int a_row = (tid * 4) >> 3;   // 0..127
    int a_col = (tid * 4) & 7;    // 0 or 4
    int b_row = (tid * 4) >> 7;   // 0..7
    int b_col = (tid * 4) & 127;

    for (int k0 = 0; k0 < K; k0 += 8) {
        float4 av = *(const float4*)&A[(size_t)(m0 + a_row) * K + k0 + a_col];
        float4 bv = *(const float4*)&Bp[(size_t)(k0 + b_row) * N + n0 + b_col];
        As[a_col + 0][a_row] = av.x;
        As[a_col + 1][a_row] = av.y;
        As[a_col + 2][a_row] = av.z;
        As[a_col + 3][a_row] = av.w;
        *(float4*)&Bs[b_row][b_col] = bv;
        __syncthreads();
        #pragma unroll
        for (int k = 0; k < 8; k++) {
            float ar[8], br[8];
            #pragma unroll
            for (int i = 0; i < 8; i++) ar[i] = As[k][ty * 8 + i];
            #pragma unroll
            for (int j = 0; j < 8; j++) br[j] = Bs[k][tx * 8 + j];
            #pragma unroll
            for (int i = 0; i < 8; i++)
                #pragma unroll
                for (int j = 0; j < 8; j++) acc[i][j] += ar[i] * br[j];
        }
        __syncthreads();
    }

    #pragma unroll
    for (int i = 0; i < 8; i++) {
        int m = m0 + ty * 8 + i;
        float bi = bias[m];
        #pragma unroll
        for (int j = 0; j < 8; j += 4) {
            int n = n0 + tx * 8 + j;
            float4 r;
            r.x = acc[i][j + 0] + bi;
            r.y = acc[i][j + 1] + bi;
            r.z = acc[i][j + 2] + bi;
            r.w = acc[i][j + 3] + bi;
            if (SKIP) {
                float4 sv = *(const float4*)&Sp[(size_t)m * N + n];
                r.x += sv.x; r.y += sv.y; r.z += sv.z; r.w += sv.w;
            }
            *(float4*)&Cp[(size_t)m * N + n] = r;
        }
    }
}

// ---------------------------------------------------------------------------
// Flash attention: block = (qtile, bh). 64 queries x full K/V sweep, hd=64.
// qkv layout [b][3C][T]; head h rows at o = h*192 + {q:0..63, k:64..127,
// v:128..191}. Output layout [b][c][t] with c = h*64 + cd  => base bh*64.
// ---------------------------------------------------------------------------
__global__ void attn_kernel(const float* __restrict__ qkv, float* __restrict__ out) {
    int qt = blockIdx.x;     // 0..15
    int bh = blockIdx.y;     // 0..63
    const float* base = qkv + (size_t)bh * 192 * NT;
    int qt0 = qt * 64;

    __shared__ float Qs[64][64];   // [c][t]
    __shared__ float KVs[64][64];  // K: [c][s]; then V: [s][c]
    __shared__ float Ps[64][64];   // [t][s]

    int tid = threadIdx.x;
    int tx = tid & 15, ty = tid >> 4;

    // Load Q tile [c][t]
    {
        int c = tid >> 4;
        int col = (tid & 15) * 4;
        #pragma unroll
        for (int r = 0; r < 4; r++)
            *(float4*)&Qs[c + r * 16][col] =
                *(const float4*)&base[(size_t)(c + r * 16) * NT + qt0 + col];
    }

    float m_run[4], l_run[4], acc[4][4];
    #pragma unroll
    for (int i = 0; i < 4; i++) {
        m_run[i] = -1e30f;
        l_run[i] = 0.f;
        #pragma unroll
        for (int j = 0; j < 4; j++) acc[i][j] = 0.f;
    }

    for (int st = 0; st < 16; st++) {
        int st0 = st * 64;
        __syncthreads();   // prev-iter PV reads of Ps/KVs done; Q load visible (st=0)
        // Load K tile [c][s]
        {
            int c = tid >> 4;
            int col = (tid & 15) * 4;
            #pragma unroll
            for (int r = 0; r < 4; r++)
                *(float4*)&KVs[c + r * 16][col] =
                    *(const float4*)&base[(size_t)(64 + c + r * 16) * NT + st0 + col];
        }
        __syncthreads();

        // Scores: S[t][s] = sum_c Q[c][t] K[c][s]
        float S[4][4];
        #pragma unroll
        for (int i = 0; i < 4; i++)
            #pragma unroll
            for (int j = 0; j < 4; j++) S[i][j] = 0.f;
        #pragma unroll 8
        for (int c = 0; c < 64; c++) {
            float qa[4], kb[4];
            #pragma unroll
            for (int i = 0; i < 4; i++) qa[i] = Qs[c][ty * 4 + i];
            #pragma unroll
            for (int j = 0; j < 4; j++) kb[j] = KVs[c][tx * 4 + j];
            #pragma unroll
            for (int i = 0; i < 4; i++)
                #pragma unroll
                for (int j = 0; j < 4; j++) S[i][j] += qa[i] * kb[j];
        }

        // Online softmax (row stats replicated across the 16 tx lanes)
        #pragma unroll
        for (int i = 0; i < 4; i++) {
            #pragma unroll
            for (int j = 0; j < 4; j++) S[i][j] *= 0.125f;   // 1/sqrt(64)
            float mx = fmaxf(fmaxf(S[i][0], S[i][1]), fmaxf(S[i][2], S[i][3]));
            #pragma unroll
            for (int off = 8; off; off >>= 1)
                mx = fmaxf(mx, __shfl_xor_sync(0xffffffffu, mx, off));
            float nm = fmaxf(m_run[i], mx);
            float al = __expf(m_run[i] - nm);
            float ps = 0.f;
            #pragma unroll
            for (int j = 0; j < 4; j++) {
                S[i][j] = __expf(S[i][j] - nm);
                ps += S[i][j];
            }
            #pragma unroll
            for (int off = 8; off; off >>= 1)
                ps += __shfl_xor_sync(0xffffffffu, ps, off);
            l_run[i] = l_run[i] * al + ps;
            m_run[i] = nm;
            #pragma unroll
            for (int j = 0; j < 4; j++) acc[i][j] *= al;
        }
        __syncthreads();   // everyone done reading K from KVs

        // Stage P, load V transposed [s][c]
        #pragma unroll
        for (int i = 0; i < 4; i++)
            #pragma unroll
            for (int j = 0; j < 4; j++) Ps[ty * 4 + i][tx * 4 + j] = S[i][j];
        {
            int c = tid & 63;
            int s4 = (tid >> 6) * 4;
            #pragma unroll
            for (int r = 0; r < 4; r++) {
                int s = s4 + r * 16;
                float4 v = *(const float4*)&base[(size_t)(128 + c) * NT + st0 + s];
                KVs[s + 0][c] = v.x;
                KVs[s + 1][c] = v.y;
                KVs[s + 2][c] = v.z;
                KVs[s + 3][c] = v.w;
            }
        }
        __syncthreads();

        // PV: acc[t][c] += sum_s P[t][s] V[s][c]
        #pragma unroll 8
        for (int s = 0; s < 64; s++) {
            float pr[4], vr[4];
            #pragma unroll
            for (int i = 0; i < 4; i++) pr[i] = Ps[ty * 4 + i][s];
            #pragma unroll
            for (int j = 0; j < 4; j++) vr[j] = KVs[s][tx * 4 + j];
            #pragma unroll
            for (int i = 0; i < 4; i++)
                #pragma unroll
                for (int j = 0; j < 4; j++) acc[i][j] += pr[i] * vr[j];
        }
    }

    // Epilogue: out[bh*64 + c][qt0 + t] = acc / l   (transpose t<->c on store)
    float* op = out + (size_t)bh * 64 * NT;
    #pragma unroll
    for (int i = 0; i < 4; i++) {
        float rinv = 1.f / l_run[i];
        #pragma unroll
        for (int j = 0; j < 4; j++)
            op[(size_t)(tx * 4 + j) * NT + qt0 + ty * 4 + i] = acc[i][j] * rinv;
    }
}

// ---------------------------------------------------------------------------
extern "C" void kernel_launch(void* const* d_in, const int* in_sizes, int n_in,
                              void* d_out, int out_size) {
    const float* x      = (const float*)d_in[0];
    const float* norm_w = (const float*)d_in[1];
    const float* norm_b = (const float*)d_in[2];
    const float* qkv_w  = (const float*)d_in[3];
    const float* qkv_b  = (const float*)d_in[4];
    const float* out_w  = (const float*)d_in[5];
    const float* out_b  = (const float*)d_in[6];
    float* out = (float*)d_out;

    float *xn, *qkvb, *attnb;
    cudaGetSymbolAddress((void**)&xn,    g_xn);
    cudaGetSymbolAddress((void**)&qkvb,  g_qkv);
    cudaGetSymbolAddress((void**)&attnb, g_attn);

    // 1. GroupNorm
    groupnorm_kernel<<<NB * NG, 256>>>(x, norm_w, norm_b);

    // 2. QKV projection: [1536,512] x [512,1024] per batch
    sgemm128<false><<<dim3(NT / 128, 3 * NC / 128, NB), 256>>>(
        qkv_w, xn, qkv_b, nullptr, qkvb, 3 * NC, NT, NC);

    // 3. Flash attention: 16 q-tiles x 64 (b,h) pairs
    attn_kernel<<<dim3(16, NB * NH), 256>>>(qkvb, attnb);

    // 4. Output projection + bias + residual skip -> d_out
    sgemm128<true><<<dim3(NT / 128, NC / 128, NB), 256>>>(
        out_w, attnb, out_b, x, out, NC, NT, NC);
}

// round 3
// speedup vs baseline: 1.4480x; 1.4480x over previous
#include <cuda_runtime.h>
#include <math.h>
#include <stdint.h>

#define NB 8
#define NC 512
#define NT 1024
#define NG 32
#define CPG 16
#define NH 8
#define HD 64

// Scratch (allocation-free rule: __device__ globals)
__device__ float g_xn[NB * NC * NT];         // GroupNorm out [b][c][t]
__device__ float g_qkv[NB * 3 * NC * NT];    // QKV           [b][3C][t]
__device__ float g_attn[NB * NC * NT];       // attention out [b][c][t]

// ---------------------------------------------------------------------------
// helpers (base sm_100 ISA only: mma.sync + cp.async, no tcgen05)
// ---------------------------------------------------------------------------
__device__ __forceinline__ uint32_t smem_u32(const void* p) {
    uint32_t a;
    asm("{ .reg .u64 t; cvta.to.shared.u64 t, %1; cvt.u32.u64 %0, t; }" : "=r"(a) : "l"(p));
    return a;
}
__device__ __forceinline__ void cp_async16(uint32_t dst, const void* src) {
    asm volatile("cp.async.cg.shared.global [%0], [%1], 16;" :: "r"(dst), "l"(src));
}
__device__ __forceinline__ void cp_commit() {
    asm volatile("cp.async.commit_group;" ::: "memory");
}
template <int N>
__device__ __forceinline__ void cp_wait() {
    asm volatile("cp.async.wait_group %0;" :: "n"(N) : "memory");
}
__device__ __forceinline__ uint32_t to_tf32(float f) {
    uint32_t u;
    asm("cvt.rna.tf32.f32 %0, %1;" : "=r"(u) : "f"(f));
    return u;
}
__device__ __forceinline__ void mma_tf32(float& d0, float& d1, float& d2, float& d3,
                                         uint32_t a0, uint32_t a1, uint32_t a2, uint32_t a3,
                                         uint32_t b0, uint32_t b1) {
    asm volatile(
        "mma.sync.aligned.m16n8k8.row.col.f32.tf32.tf32.f32 "
        "{%0,%1,%2,%3}, {%4,%5,%6,%7}, {%8,%9}, {%0,%1,%2,%3};"
        : "+f"(d0), "+f"(d1), "+f"(d2), "+f"(d3)
        : "r"(a0), "r"(a1), "r"(a2), "r"(a3), "r"(b0), "r"(b1));
}

// ---------------------------------------------------------------------------
// GroupNorm(32, 512): one block per (b, group) -> g_xn [b][c][t]
// ---------------------------------------------------------------------------
__global__ void groupnorm_kernel(const float* __restrict__ x,
                                 const float* __restrict__ nw,
                                 const float* __restrict__ nb) {
    int b = blockIdx.x >> 5;
    int g = blockIdx.x & 31;
    const float* xp = x + (size_t)(b * NC + g * CPG) * NT;
    float* op = g_xn + (size_t)(b * NC + g * CPG) * NT;
    int tid = threadIdx.x;

    float s = 0.f, sq = 0.f;
    const float4* xp4 = (const float4*)xp;
    const int N4 = CPG * NT / 4;
    for (int i = tid; i < N4; i += 256) {
        float4 v = xp4[i];
        s  += v.x + v.y + v.z + v.w;
        sq += v.x * v.x + v.y * v.y + v.z * v.z + v.w * v.w;
    }
    __shared__ float rs[8], rq[8];
    #pragma unroll
    for (int off = 16; off; off >>= 1) {
        s  += __shfl_xor_sync(0xffffffffu, s, off);
        sq += __shfl_xor_sync(0xffffffffu, sq, off);
    }
    if ((tid & 31) == 0) { rs[tid >> 5] = s; rq[tid >> 5] = sq; }
    __syncthreads();
    if (tid < 32) {
        s  = (tid < 8) ? rs[tid] : 0.f;
        sq = (tid < 8) ? rq[tid] : 0.f;
        #pragma unroll
        for (int off = 4; off; off >>= 1) {
            s  += __shfl_xor_sync(0xffffffffu, s, off);
            sq += __shfl_xor_sync(0xffffffffu, sq, off);
        }
        if (tid == 0) { rs[0] = s; rq[0] = sq; }
    }
    __syncthreads();
    const float invn = 1.f / (CPG * NT);
    float mean = rs[0] * invn;
    float var = rq[0] * invn - mean * mean;
    float rinv = rsqrtf(var + 1e-5f);

    float4* op4 = (float4*)op;
    for (int i = tid; i < N4; i += 256) {
        int c = g * CPG + (i >> 8);
        float w = nw[c] * rinv;
        float bia = nb[c] - mean * w;
        float4 v = xp4[i];
        v.x = v.x * w + bia;
        v.y = v.y * w + bia;
        v.z = v.z * w + bia;
        v.w = v.w * w + bia;
        op4[i] = v;
    }
}

// ---------------------------------------------------------------------------
// tf32 mma.sync GEMM: C[bz][m][n] = sum_k A[m][k] * B[bz][k][n] + bias[m]
//                     (+ skip[bz][m][n] if SKIP)
// CTA 128x128, BK=16, 8 warps (2x4), warp tile 64x32, double-buffered cp.async.
// K = 512, N = 1024 fixed. A shared across batch.
// ---------------------------------------------------------------------------
#define GK 512
#define GN 1024
#define ASTRIDE 20   // floats per A smem row (128 rows)
#define BSTRIDE 136  // floats per B smem row (16 rows)

template <bool SKIP>
__global__ void __launch_bounds__(256) tf32mma_gemm(
    const float* __restrict__ A, const float* __restrict__ Bm,
    const float* __restrict__ bias, const float* __restrict__ skip,
    float* __restrict__ Cm, int M) {
    __shared__ float As[2][128 * ASTRIDE];
    __shared__ float Bs[2][16 * BSTRIDE];

    int tid = threadIdx.x;
    int bz = blockIdx.z;
    int m0 = blockIdx.y * 128, n0 = blockIdx.x * 128;
    const float* Bp = Bm + (size_t)bz * GK * GN;
    float* Cp = Cm + (size_t)bz * M * GN;

    int lane = tid & 31;
    int wid = tid >> 5;
    int g = lane >> 2, tig = lane & 3;
    int warp_m = wid >> 2;        // 0..1
    int warp_n = wid & 3;         // 0..3

    // Per-thread cp.async indices (2 chunks of 16B for A, 2 for B per stage)
    int a_m[2], a_k[2], b_k[2], b_n[2];
    #pragma unroll
    for (int i = 0; i < 2; i++) {
        int idx = tid + i * 256;
        a_m[i] = idx >> 2;          // 0..127
        a_k[i] = (idx & 3) * 4;     // 0,4,8,12
        b_k[i] = idx >> 5;          // 0..15
        b_n[i] = (idx & 31) * 4;    // 0..124
    }
    uint32_t asb[2] = {smem_u32(As[0]), smem_u32(As[1])};
    uint32_t bsb[2] = {smem_u32(Bs[0]), smem_u32(Bs[1])};

    auto issue = [&](int c) {
        int s = c & 1;
        int k0 = c * 16;
        #pragma unroll
        for (int i = 0; i < 2; i++) {
            cp_async16(asb[s] + (a_m[i] * ASTRIDE + a_k[i]) * 4,
                       &A[(size_t)(m0 + a_m[i]) * GK + k0 + a_k[i]]);
            cp_async16(bsb[s] + (b_k[i] * BSTRIDE + b_n[i]) * 4,
                       &Bp[(size_t)(k0 + b_k[i]) * GN + n0 + b_n[i]]);
        }
        cp_commit();
    };

    float acc[4][4][4];
    #pragma unroll
    for (int mi = 0; mi < 4; mi++)
        #pragma unroll
        for (int ni = 0; ni < 4; ni++)
            #pragma unroll
            for (int r = 0; r < 4; r++) acc[mi][ni][r] = 0.f;

    issue(0);

    const int NCHUNK = GK / 16;   // 32
    for (int c = 0; c < NCHUNK; c++) {
        int s = c & 1;
        if (c + 1 < NCHUNK) { issue(c + 1); cp_wait<1>(); }
        else cp_wait<0>();
        __syncthreads();

        const float* as = As[s];
        const float* bs = Bs[s];
        #pragma unroll
        for (int kk = 0; kk < 16; kk += 8) {
            uint32_t af[4][4];
            #pragma unroll
            for (int mi = 0; mi < 4; mi++) {
                int mr = warp_m * 64 + mi * 16 + g;
                af[mi][0] = to_tf32(as[(mr    ) * ASTRIDE + kk + tig]);
                af[mi][1] = to_tf32(as[(mr + 8) * ASTRIDE + kk + tig]);
                af[mi][2] = to_tf32(as[(mr    ) * ASTRIDE + kk + tig + 4]);
                af[mi][3] = to_tf32(as[(mr + 8) * ASTRIDE + kk + tig + 4]);
            }
            uint32_t bf[4][2];
            #pragma unroll
            for (int ni = 0; ni < 4; ni++) {
                int n = warp_n * 32 + ni * 8 + g;
                bf[ni][0] = to_tf32(bs[(kk + tig    ) * BSTRIDE + n]);
                bf[ni][1] = to_tf32(bs[(kk + tig + 4) * BSTRIDE + n]);
            }
            #pragma unroll
            for (int mi = 0; mi < 4; mi++)
                #pragma unroll
                for (int ni = 0; ni < 4; ni++)
                    mma_tf32(acc[mi][ni][0], acc[mi][ni][1], acc[mi][ni][2], acc[mi][ni][3],
                             af[mi][0], af[mi][1], af[mi][2], af[mi][3],
                             bf[ni][0], bf[ni][1]);
        }
        __syncthreads();
    }

    // Epilogue: c0 (r, 2tig) c1 (r, 2tig+1) c2 (r+8, 2tig) c3 (r+8, 2tig+1)
    #pragma unroll
    for (int mi = 0; mi < 4; mi++) {
        int r0 = m0 + warp_m * 64 + mi * 16 + g;
        int r1 = r0 + 8;
        float bi0 = bias[r0], bi1 = bias[r1];
        #pragma unroll
        for (int ni = 0; ni < 4; ni++) {
            int n = n0 + warp_n * 32 + ni * 8 + 2 * tig;
            float2 v0, v1;
            v0.x = acc[mi][ni][0] + bi0;
            v0.y = acc[mi][ni][1] + bi0;
            v1.x = acc[mi][ni][2] + bi1;
            v1.y = acc[mi][ni][3] + bi1;
            if (SKIP) {
                const float* sp = skip + (size_t)bz * M * GN;
                float2 s0 = *(const float2*)&sp[(size_t)r0 * GN + n];
                float2 s1 = *(const float2*)&sp[(size_t)r1 * GN + n];
                v0.x += s0.x; v0.y += s0.y;
                v1.x += s1.x; v1.y += s1.y;
            }
            *(float2*)&Cp[(size_t)r0 * GN + n] = v0;
            *(float2*)&Cp[(size_t)r1 * GN + n] = v1;
        }
    }
}

// ---------------------------------------------------------------------------
// Flash attention (fp32 scalar, R1-passing version): out [b][c][t]
// ---------------------------------------------------------------------------
__global__ void attn_kernel(const float* __restrict__ qkv, float* __restrict__ out) {
    int qt = blockIdx.x;     // 0..15
    int bh = blockIdx.y;     // 0..63
    const float* base = qkv + (size_t)bh * 192 * NT;
    int qt0 = qt * 64;

    __shared__ float Qs[64][64];
    __shared__ float KVs[64][64];
    __shared__ float Ps[64][64];

    int tid = threadIdx.x;
    int tx = tid & 15, ty = tid >> 4;

    {
        int c = tid >> 4;
        int col = (tid & 15) * 4;
        #pragma unroll
        for (int r = 0; r < 4; r++)
            *(float4*)&Qs[c + r * 16][col] =
                *(const float4*)&base[(size_t)(c + r * 16) * NT + qt0 + col];
    }

    float m_run[4], l_run[4], acc[4][4];
    #pragma unroll
    for (int i = 0; i < 4; i++) {
        m_run[i] = -1e30f;
        l_run[i] = 0.f;
        #pragma unroll
        for (int j = 0; j < 4; j++) acc[i][j] = 0.f;
    }

    for (int st = 0; st < 16; st++) {
        int st0 = st * 64;
        __syncthreads();
        {
            int c = tid >> 4;
            int col = (tid & 15) * 4;
            #pragma unroll
            for (int r = 0; r < 4; r++)
                *(float4*)&KVs[c + r * 16][col] =
                    *(const float4*)&base[(size_t)(64 + c + r * 16) * NT + st0 + col];
        }
        __syncthreads();

        float S[4][4];
        #pragma unroll
        for (int i = 0; i < 4; i++)
            #pragma unroll
            for (int j = 0; j < 4; j++) S[i][j] = 0.f;
        #pragma unroll 8
        for (int c = 0; c < 64; c++) {
            float qa[4], kb[4];
            #pragma unroll
            for (int i = 0; i < 4; i++) qa[i] = Qs[c][ty * 4 + i];
            #pragma unroll
            for (int j = 0; j < 4; j++) kb[j] = KVs[c][tx * 4 + j];
            #pragma unroll
            for (int i = 0; i < 4; i++)
                #pragma unroll
                for (int j = 0; j < 4; j++) S[i][j] += qa[i] * kb[j];
        }

        #pragma unroll
        for (int i = 0; i < 4; i++) {
            #pragma unroll
            for (int j = 0; j < 4; j++) S[i][j] *= 0.125f;
            float mx = fmaxf(fmaxf(S[i][0], S[i][1]), fmaxf(S[i][2], S[i][3]));
            #pragma unroll
            for (int off = 8; off; off >>= 1)
                mx = fmaxf(mx, __shfl_xor_sync(0xffffffffu, mx, off));
            float nm = fmaxf(m_run[i], mx);
            float al = __expf(m_run[i] - nm);
            float ps = 0.f;
            #pragma unroll
            for (int j = 0; j < 4; j++) {
                S[i][j] = __expf(S[i][j] - nm);
                ps += S[i][j];
            }
            #pragma unroll
            for (int off = 8; off; off >>= 1)
                ps += __shfl_xor_sync(0xffffffffu, ps, off);
            l_run[i] = l_run[i] * al + ps;
            m_run[i] = nm;
            #pragma unroll
            for (int j = 0; j < 4; j++) acc[i][j] *= al;
        }
        __syncthreads();

        #pragma unroll
        for (int i = 0; i < 4; i++)
            #pragma unroll
            for (int j = 0; j < 4; j++) Ps[ty * 4 + i][tx * 4 + j] = S[i][j];
        {
            int c = tid & 63;
            int s4 = (tid >> 6) * 4;
            #pragma unroll
            for (int r = 0; r < 4; r++) {
                int s = s4 + r * 16;
                float4 v = *(const float4*)&base[(size_t)(128 + c) * NT + st0 + s];
                KVs[s + 0][c] = v.x;
                KVs[s + 1][c] = v.y;
                KVs[s + 2][c] = v.z;
                KVs[s + 3][c] = v.w;
            }
        }
        __syncthreads();

        #pragma unroll 8
        for (int s = 0; s < 64; s++) {
            float pr[4], vr[4];
            #pragma unroll
            for (int i = 0; i < 4; i++) pr[i] = Ps[ty * 4 + i][s];
            #pragma unroll
            for (int j = 0; j < 4; j++) vr[j] = KVs[s][tx * 4 + j];
            #pragma unroll
            for (int i = 0; i < 4; i++)
                #pragma unroll
                for (int j = 0; j < 4; j++) acc[i][j] += pr[i] * vr[j];
        }
    }

    float* op = out + (size_t)bh * 64 * NT;
    #pragma unroll
    for (int i = 0; i < 4; i++) {
        float rinv = 1.f / l_run[i];
        #pragma unroll
        for (int j = 0; j < 4; j++)
            op[(size_t)(tx * 4 + j) * NT + qt0 + ty * 4 + i] = acc[i][j] * rinv;
    }
}

// ---------------------------------------------------------------------------
extern "C" void kernel_launch(void* const* d_in, const int* in_sizes, int n_in,
                              void* d_out, int out_size) {
    const float* x      = (const float*)d_in[0];
    const float* norm_w = (const float*)d_in[1];
    const float* norm_b = (const float*)d_in[2];
    const float* qkv_w  = (const float*)d_in[3];
    const float* qkv_b  = (const float*)d_in[4];
    const float* out_w  = (const float*)d_in[5];
    const float* out_b  = (const float*)d_in[6];
    float* out = (float*)d_out;

    float *xn, *qkvb, *attnb;
    cudaGetSymbolAddress((void**)&xn,    g_xn);
    cudaGetSymbolAddress((void**)&qkvb,  g_qkv);
    cudaGetSymbolAddress((void**)&attnb, g_attn);

    // 1. GroupNorm -> g_xn [b][c][t]
    groupnorm_kernel<<<NB * NG, 256>>>(x, norm_w, norm_b);

    // 2. QKV projection (mma.sync tf32): [1536,512] @ [512,1024] per batch
    tf32mma_gemm<false><<<dim3(GN / 128, 1536 / 128, NB), 256>>>(
        qkv_w, xn, qkv_b, nullptr, qkvb, 1536);

    // 3. Flash attention -> g_attn [b][c][t]
    attn_kernel<<<dim3(16, NB * NH), 256>>>(qkvb, attnb);

    // 4. Output projection + bias + skip (mma.sync tf32) -> d_out
    tf32mma_gemm<true><<<dim3(GN / 128, NC / 128, NB), 256>>>(
        out_w, attnb, out_b, x, out, NC);
}

// round 5
// speedup vs baseline: 2.4112x; 1.6652x over previous
#include <cuda_runtime.h>
#include <math.h>
#include <stdint.h>

#define NB 8
#define NC 512
#define NT 1024
#define NG 32
#define CPG 16
#define NH 8
#define HD 64

// Scratch (allocation-free rule: __device__ globals)
__device__ float g_xn[NB * NC * NT];         // GroupNorm out [b][c][t] (tf32-rounded)
__device__ float g_qkv[NB * 3 * NC * NT];    // QKV           [b][3C][t] (tf32-rounded)
__device__ float g_attn[NB * NC * NT];       // attention out [b][c][t] (tf32-rounded)
__device__ float g_qkv_w_r[1536 * NC];       // rounded qkv weights
__device__ float g_out_w_r[NC * NC];         // rounded out weights

// ---------------------------------------------------------------------------
// helpers (base sm_100 ISA: mma.sync + cp.async)
// ---------------------------------------------------------------------------
__device__ __forceinline__ uint32_t smem_u32(const void* p) {
    uint32_t a;
    asm("{ .reg .u64 t; cvta.to.shared.u64 t, %1; cvt.u32.u64 %0, t; }" : "=r"(a) : "l"(p));
    return a;
}
__device__ __forceinline__ void cp_async16(uint32_t dst, const void* src) {
    asm volatile("cp.async.cg.shared.global [%0], [%1], 16;" :: "r"(dst), "l"(src));
}
__device__ __forceinline__ void cp_commit() {
    asm volatile("cp.async.commit_group;" ::: "memory");
}
template <int N>
__device__ __forceinline__ void cp_wait() {
    asm volatile("cp.async.wait_group %0;" :: "n"(N) : "memory");
}
__device__ __forceinline__ float rnd_tf32(float f) {
    uint32_t u;
    asm("cvt.rna.tf32.f32 %0, %1;" : "=r"(u) : "f"(f));
    return __uint_as_float(u);
}
__device__ __forceinline__ void mma_tf32(float& d0, float& d1, float& d2, float& d3,
                                         uint32_t a0, uint32_t a1, uint32_t a2, uint32_t a3,
                                         uint32_t b0, uint32_t b1) {
    asm volatile(
        "mma.sync.aligned.m16n8k8.row.col.f32.tf32.tf32.f32 "
        "{%0,%1,%2,%3}, {%4,%5,%6,%7}, {%8,%9}, {%0,%1,%2,%3};"
        : "+f"(d0), "+f"(d1), "+f"(d2), "+f"(d3)
        : "r"(a0), "r"(a1), "r"(a2), "r"(a3), "r"(b0), "r"(b1));
}

// ---------------------------------------------------------------------------
// Weight pre-rounding (RNA to tf32) — keeps the mma inner loops cvt-free
// ---------------------------------------------------------------------------
__global__ void round_kernel(const float* __restrict__ src, float* __restrict__ dst, int n4) {
    int i = blockIdx.x * 256 + threadIdx.x;
    if (i < n4) {
        float4 v = ((const float4*)src)[i];
        v.x = rnd_tf32(v.x); v.y = rnd_tf32(v.y);
        v.z = rnd_tf32(v.z); v.w = rnd_tf32(v.w);
        ((float4*)dst)[i] = v;
    }
}

// ---------------------------------------------------------------------------
// GroupNorm(32, 512) -> g_xn [b][c][t], outputs tf32-rounded
// ---------------------------------------------------------------------------
__global__ void groupnorm_kernel(const float* __restrict__ x,
                                 const float* __restrict__ nw,
                                 const float* __restrict__ nb) {
    int b = blockIdx.x >> 5;
    int g = blockIdx.x & 31;
    const float* xp = x + (size_t)(b * NC + g * CPG) * NT;
    float* op = g_xn + (size_t)(b * NC + g * CPG) * NT;
    int tid = threadIdx.x;

    float s = 0.f, sq = 0.f;
    const float4* xp4 = (const float4*)xp;
    const int N4 = CPG * NT / 4;
    for (int i = tid; i < N4; i += 256) {
        float4 v = xp4[i];
        s  += v.x + v.y + v.z + v.w;
        sq += v.x * v.x + v.y * v.y + v.z * v.z + v.w * v.w;
    }
    __shared__ float rs[8], rq[8];
    #pragma unroll
    for (int off = 16; off; off >>= 1) {
        s  += __shfl_xor_sync(0xffffffffu, s, off);
        sq += __shfl_xor_sync(0xffffffffu, sq, off);
    }
    if ((tid & 31) == 0) { rs[tid >> 5] = s; rq[tid >> 5] = sq; }
    __syncthreads();
    if (tid < 32) {
        s  = (tid < 8) ? rs[tid] : 0.f;
        sq = (tid < 8) ? rq[tid] : 0.f;
        #pragma unroll
        for (int off = 4; off; off >>= 1) {
            s  += __shfl_xor_sync(0xffffffffu, s, off);
            sq += __shfl_xor_sync(0xffffffffu, sq, off);
        }
        if (tid == 0) { rs[0] = s; rq[0] = sq; }
    }
    __syncthreads();
    const float invn = 1.f / (CPG * NT);
    float mean = rs[0] * invn;
    float var = rq[0] * invn - mean * mean;
    float rinv = rsqrtf(var + 1e-5f);

    float4* op4 = (float4*)op;
    for (int i = tid; i < N4; i += 256) {
        int c = g * CPG + (i >> 8);
        float w = nw[c] * rinv;
        float bia = nb[c] - mean * w;
        float4 v = xp4[i];
        v.x = rnd_tf32(v.x * w + bia);
        v.y = rnd_tf32(v.y * w + bia);
        v.z = rnd_tf32(v.z * w + bia);
        v.w = rnd_tf32(v.w * w + bia);
        op4[i] = v;
    }
}

// ---------------------------------------------------------------------------
// tf32 mma.sync GEMM: C[bz][m][n] = sum_k A[m][k] * B[bz][k][n] + bias[m]
// A pre-rounded; B pre-rounded. ROUND: round outputs (when consumer is mma).
// ---------------------------------------------------------------------------
#define GK 512
#define GN 1024
#define ASTRIDE 20
#define BSTRIDE 136

template <bool SKIP, bool ROUND>
__global__ void __launch_bounds__(256) tf32mma_gemm(
    const float* __restrict__ A, const float* __restrict__ Bm,
    const float* __restrict__ bias, const float* __restrict__ skip,
    float* __restrict__ Cm, int M) {
    __shared__ float As[2][128 * ASTRIDE];
    __shared__ float Bs[2][16 * BSTRIDE];

    int tid = threadIdx.x;
    int bz = blockIdx.z;
    int m0 = blockIdx.y * 128, n0 = blockIdx.x * 128;
    const float* Bp = Bm + (size_t)bz * GK * GN;
    float* Cp = Cm + (size_t)bz * M * GN;

    int lane = tid & 31;
    int wid = tid >> 5;
    int g = lane >> 2, tig = lane & 3;
    int warp_m = wid >> 2;
    int warp_n = wid & 3;

    int a_m[2], a_k[2], b_k[2], b_n[2];
    #pragma unroll
    for (int i = 0; i < 2; i++) {
        int idx = tid + i * 256;
        a_m[i] = idx >> 2;
        a_k[i] = (idx & 3) * 4;
        b_k[i] = idx >> 5;
        b_n[i] = (idx & 31) * 4;
    }
    uint32_t asb[2] = {smem_u32(As[0]), smem_u32(As[1])};
    uint32_t bsb[2] = {smem_u32(Bs[0]), smem_u32(Bs[1])};

    auto issue = [&](int c) {
        int s = c & 1;
        int k0 = c * 16;
        #pragma unroll
        for (int i = 0; i < 2; i++) {
            cp_async16(asb[s] + (a_m[i] * ASTRIDE + a_k[i]) * 4,
                       &A[(size_t)(m0 + a_m[i]) * GK + k0 + a_k[i]]);
            cp_async16(bsb[s] + (b_k[i] * BSTRIDE + b_n[i]) * 4,
                       &Bp[(size_t)(k0 + b_k[i]) * GN + n0 + b_n[i]]);
        }
        cp_commit();
    };

    float acc[4][4][4];
    #pragma unroll
    for (int mi = 0; mi < 4; mi++)
        #pragma unroll
        for (int ni = 0; ni < 4; ni++)
            #pragma unroll
            for (int r = 0; r < 4; r++) acc[mi][ni][r] = 0.f;

    issue(0);

    const int NCHUNK = GK / 16;
    for (int c = 0; c < NCHUNK; c++) {
        int s = c & 1;
        if (c + 1 < NCHUNK) { issue(c + 1); cp_wait<1>(); }
        else cp_wait<0>();
        __syncthreads();

        const float* as = As[s];
        const float* bs = Bs[s];
        #pragma unroll
        for (int kk = 0; kk < 16; kk += 8) {
            uint32_t af[4][4];
            #pragma unroll
            for (int mi = 0; mi < 4; mi++) {
                int mr = warp_m * 64 + mi * 16 + g;
                af[mi][0] = __float_as_uint(as[(mr    ) * ASTRIDE + kk + tig]);
                af[mi][1] = __float_as_uint(as[(mr + 8) * ASTRIDE + kk + tig]);
                af[mi][2] = __float_as_uint(as[(mr    ) * ASTRIDE + kk + tig + 4]);
                af[mi][3] = __float_as_uint(as[(mr + 8) * ASTRIDE + kk + tig + 4]);
            }
            uint32_t bf[4][2];
            #pragma unroll
            for (int ni = 0; ni < 4; ni++) {
                int n = warp_n * 32 + ni * 8 + g;
                bf[ni][0] = __float_as_uint(bs[(kk + tig    ) * BSTRIDE + n]);
                bf[ni][1] = __float_as_uint(bs[(kk + tig + 4) * BSTRIDE + n]);
            }
            #pragma unroll
            for (int mi = 0; mi < 4; mi++)
                #pragma unroll
                for (int ni = 0; ni < 4; ni++)
                    mma_tf32(acc[mi][ni][0], acc[mi][ni][1], acc[mi][ni][2], acc[mi][ni][3],
                             af[mi][0], af[mi][1], af[mi][2], af[mi][3],
                             bf[ni][0], bf[ni][1]);
        }
        __syncthreads();
    }

    #pragma unroll
    for (int mi = 0; mi < 4; mi++) {
        int r0 = m0 + warp_m * 64 + mi * 16 + g;
        int r1 = r0 + 8;
        float bi0 = bias[r0], bi1 = bias[r1];
        #pragma unroll
        for (int ni = 0; ni < 4; ni++) {
            int n = n0 + warp_n * 32 + ni * 8 + 2 * tig;
            float2 v0, v1;
            v0.x = acc[mi][ni][0] + bi0;
            v0.y = acc[mi][ni][1] + bi0;
            v1.x = acc[mi][ni][2] + bi1;
            v1.y = acc[mi][ni][3] + bi1;
            if (SKIP) {
                const float* sp = skip + (size_t)bz * M * GN;
                float2 s0 = *(const float2*)&sp[(size_t)r0 * GN + n];
                float2 s1 = *(const float2*)&sp[(size_t)r1 * GN + n];
                v0.x += s0.x; v0.y += s0.y;
                v1.x += s1.x; v1.y += s1.y;
            }
            if (ROUND) {
                v0.x = rnd_tf32(v0.x); v0.y = rnd_tf32(v0.y);
                v1.x = rnd_tf32(v1.x); v1.y = rnd_tf32(v1.y);
            }
            *(float2*)&Cp[(size_t)r0 * GN + n] = v0;
            *(float2*)&Cp[(size_t)r1 * GN + n] = v1;
        }
    }
}

// ---------------------------------------------------------------------------
// Flash attention, mma.sync tf32.  Block: 128 q rows x (b,h). s-tiles of 64.
// S phase:  S[t][s] = Q^T K   (warps partition t: 8 x 16)
// PV phase: O^T[c][t] += V[c][s] P^T[s][t]  (warps: 4 in c x 2 in t)
// V used in native [c][s] layout; output lands in [c][t] layout directly.
// ---------------------------------------------------------------------------
#define QTS 132
#define KSS 68
#define PTS 132
#define ATT_SMEM (138240)

__global__ void __launch_bounds__(256) attn_mma(const float* __restrict__ qkv,
                                                float* __restrict__ out) {
    extern __shared__ float sm[];
    float* Qs  = sm;            // [64][132]  Q  [c][t]
    float* KsB = sm + 8448;     // [2][64][68] K [c][s]
    float* VsB = sm + 17152;    // [2][64][68] V [c][s]
    float* Pt  = sm + 25856;    // [64][132]  P^T [s][t]
    float* al_s = sm + 34304;   // [128]
    float* l_s  = sm + 34432;   // [128]

    int tid = threadIdx.x;
    int lane = tid & 31, wid = tid >> 5;
    int g = lane >> 2, tig = lane & 3;
    int qt0 = blockIdx.x * 128;
    int bh = blockIdx.y;
    const float* base = qkv + (size_t)bh * 192 * NT;

    uint32_t qsa = smem_u32(Qs), ksa = smem_u32(KsB), vsa = smem_u32(VsB);

    // Q load (2048 float4)
    #pragma unroll
    for (int i = 0; i < 8; i++) {
        int idx = tid + i * 256;
        int row = idx >> 5, c4 = idx & 31;
        cp_async16(qsa + (row * QTS + c4 * 4) * 4,
                   &base[(size_t)row * NT + qt0 + c4 * 4]);
    }
    auto load_kv = [&](int st) {
        int s = st & 1;
        int s0 = st * 64;
        #pragma unroll
        for (int i = 0; i < 4; i++) {
            int idx = tid + i * 256;
            int row = idx >> 4, c4 = idx & 15;
            cp_async16(ksa + (s * 4352 + row * KSS + c4 * 4) * 4,
                       &base[(size_t)(64 + row) * NT + s0 + c4 * 4]);
            cp_async16(vsa + (s * 4352 + row * KSS + c4 * 4) * 4,
                       &base[(size_t)(128 + row) * NT + s0 + c4 * 4]);
        }
        cp_commit();
    };
    load_kv(0);   // group0 = Q + K0 + V0

    float m_run[2] = {-1e30f, -1e30f}, l_run[2] = {0.f, 0.f};
    float acc[8][4];
    #pragma unroll
    for (int ni = 0; ni < 8; ni++)
        #pragma unroll
        for (int j = 0; j < 4; j++) acc[ni][j] = 0.f;

    int tq0 = wid * 16;             // S-phase t rows for this warp
    int pv_m0 = (wid & 3) * 16;     // PV c rows
    int pv_n0 = (wid >> 2) * 64;    // PV t cols

    for (int st = 0; st < 16; st++) {
        int s = st & 1;
        __syncthreads();            // prev PV done before KV issue / Pt rewrite
        if (st + 1 < 16) { load_kv(st + 1); cp_wait<1>(); }
        else cp_wait<0>();
        __syncthreads();

        const float* Ks = KsB + s * 4352;
        const float* Vsc = VsB + s * 4352;

        // S = Q^T K
        float S[8][4];
        #pragma unroll
        for (int ni = 0; ni < 8; ni++)
            #pragma unroll
            for (int j = 0; j < 4; j++) S[ni][j] = 0.f;
        #pragma unroll
        for (int kk = 0; kk < 64; kk += 8) {
            uint32_t a0 = __float_as_uint(Qs[(kk + tig) * QTS + tq0 + g]);
            uint32_t a1 = __float_as_uint(Qs[(kk + tig) * QTS + tq0 + g + 8]);
            uint32_t a2 = __float_as_uint(Qs[(kk + tig + 4) * QTS + tq0 + g]);
            uint32_t a3 = __float_as_uint(Qs[(kk + tig + 4) * QTS + tq0 + g + 8]);
            #pragma unroll
            for (int ni = 0; ni < 8; ni++) {
                uint32_t b0 = __float_as_uint(Ks[(kk + tig) * KSS + ni * 8 + g]);
                uint32_t b1 = __float_as_uint(Ks[(kk + tig + 4) * KSS + ni * 8 + g]);
                mma_tf32(S[ni][0], S[ni][1], S[ni][2], S[ni][3], a0, a1, a2, a3, b0, b1);
            }
        }

        // online softmax: rows g (r0) and g+8 (r1) of this warp's 16-row slice
        float mx0 = -1e30f, mx1 = -1e30f;
        #pragma unroll
        for (int ni = 0; ni < 8; ni++) {
            #pragma unroll
            for (int j = 0; j < 4; j++) S[ni][j] *= 0.125f;
            mx0 = fmaxf(mx0, fmaxf(S[ni][0], S[ni][1]));
            mx1 = fmaxf(mx1, fmaxf(S[ni][2], S[ni][3]));
        }
        mx0 = fmaxf(mx0, __shfl_xor_sync(0xffffffffu, mx0, 1));
        mx0 = fmaxf(mx0, __shfl_xor_sync(0xffffffffu, mx0, 2));
        mx1 = fmaxf(mx1, __shfl_xor_sync(0xffffffffu, mx1, 1));
        mx1 = fmaxf(mx1, __shfl_xor_sync(0xffffffffu, mx1, 2));
        float nm0 = fmaxf(m_run[0], mx0), nm1 = fmaxf(m_run[1], mx1);
        float al0 = __expf(m_run[0] - nm0), al1 = __expf(m_run[1] - nm1);
        float ps0 = 0.f, ps1 = 0.f;
        #pragma unroll
        for (int ni = 0; ni < 8; ni++) {
            S[ni][0] = __expf(S[ni][0] - nm0);
            S[ni][1] = __expf(S[ni][1] - nm0);
            S[ni][2] = __expf(S[ni][2] - nm1);
            S[ni][3] = __expf(S[ni][3] - nm1);
            ps0 += S[ni][0] + S[ni][1];
            ps1 += S[ni][2] + S[ni][3];
        }
        ps0 += __shfl_xor_sync(0xffffffffu, ps0, 1);
        ps0 += __shfl_xor_sync(0xffffffffu, ps0, 2);
        ps1 += __shfl_xor_sync(0xffffffffu, ps1, 1);
        ps1 += __shfl_xor_sync(0xffffffffu, ps1, 2);
        l_run[0] = l_run[0] * al0 + ps0;
        l_run[1] = l_run[1] * al1 + ps1;
        m_run[0] = nm0;
        m_run[1] = nm1;

        // stage P^T[s][t] (tf32-rounded) + broadcast alpha
        #pragma unroll
        for (int ni = 0; ni < 8; ni++) {
            int sc = ni * 8 + 2 * tig;
            Pt[(sc    ) * PTS + tq0 + g    ] = rnd_tf32(S[ni][0]);
            Pt[(sc + 1) * PTS + tq0 + g    ] = rnd_tf32(S[ni][1]);
            Pt[(sc    ) * PTS + tq0 + g + 8] = rnd_tf32(S[ni][2]);
            Pt[(sc + 1) * PTS + tq0 + g + 8] = rnd_tf32(S[ni][3]);
        }
        if (tig == 0) {
            al_s[tq0 + g] = al0;
            al_s[tq0 + g + 8] = al1;
        }
        __syncthreads();

        // rescale running accumulators by alpha of each t-column
        #pragma unroll
        for (int ni = 0; ni < 8; ni++) {
            float aA = al_s[pv_n0 + ni * 8 + 2 * tig];
            float aB = al_s[pv_n0 + ni * 8 + 2 * tig + 1];
            acc[ni][0] *= aA; acc[ni][1] *= aB;
            acc[ni][2] *= aA; acc[ni][3] *= aB;
        }

        // O^T += V P^T
        #pragma unroll
        for (int kk = 0; kk < 64; kk += 8) {
            uint32_t a0 = __float_as_uint(Vsc[(pv_m0 + g) * KSS + kk + tig]);
            uint32_t a1 = __float_as_uint(Vsc[(pv_m0 + g + 8) * KSS + kk + tig]);
            uint32_t a2 = __float_as_uint(Vsc[(pv_m0 + g) * KSS + kk + tig + 4]);
            uint32_t a3 = __float_as_uint(Vsc[(pv_m0 + g + 8) * KSS + kk + tig + 4]);
            #pragma unroll
            for (int ni = 0; ni < 8; ni++) {
                uint32_t b0 = __float_as_uint(Pt[(kk + tig) * PTS + pv_n0 + ni * 8 + g]);
                uint32_t b1 = __float_as_uint(Pt[(kk + tig + 4) * PTS + pv_n0 + ni * 8 + g]);
                mma_tf32(acc[ni][0], acc[ni][1], acc[ni][2], acc[ni][3],
                         a0, a1, a2, a3, b0, b1);
            }
        }
    }

    if (tig == 0) {
        l_s[tq0 + g] = l_run[0];
        l_s[tq0 + g + 8] = l_run[1];
    }
    __syncthreads();

    // epilogue: normalize, round (consumer is out-proj mma), store [c][t]
    float* op = out + (size_t)bh * 64 * NT;
    #pragma unroll
    for (int ni = 0; ni < 8; ni++) {
        int t = pv_n0 + ni * 8 + 2 * tig;
        float ia = 1.f / l_s[t], ib = 1.f / l_s[t + 1];
        int c0 = pv_m0 + g, c1 = c0 + 8;
        float2 v0, v1;
        v0.x = rnd_tf32(acc[ni][0] * ia);
        v0.y = rnd_tf32(acc[ni][1] * ib);
        v1.x = rnd_tf32(acc[ni][2] * ia);
        v1.y = rnd_tf32(acc[ni][3] * ib);
        *(float2*)&op[(size_t)c0 * NT + qt0 + t] = v0;
        *(float2*)&op[(size_t)c1 * NT + qt0 + t] = v1;
    }
}

// ---------------------------------------------------------------------------
extern "C" void kernel_launch(void* const* d_in, const int* in_sizes, int n_in,
                              void* d_out, int out_size) {
    const float* x      = (const float*)d_in[0];
    const float* norm_w = (const float*)d_in[1];
    const float* norm_b = (const float*)d_in[2];
    const float* qkv_w  = (const float*)d_in[3];
    const float* qkv_b  = (const float*)d_in[4];
    const float* out_w  = (const float*)d_in[5];
    const float* out_b  = (const float*)d_in[6];
    float* out = (float*)d_out;

    float *qkvwr, *outwr, *xn, *qkvb, *attnb;
    cudaGetSymbolAddress((void**)&qkvwr, g_qkv_w_r);
    cudaGetSymbolAddress((void**)&outwr, g_out_w_r);
    cudaGetSymbolAddress((void**)&xn,    g_xn);
    cudaGetSymbolAddress((void**)&qkvb,  g_qkv);
    cudaGetSymbolAddress((void**)&attnb, g_attn);

    cudaFuncSetAttribute(attn_mma, cudaFuncAttributeMaxDynamicSharedMemorySize, ATT_SMEM);

    // 0. pre-round weights to tf32 (RNA)
    round_kernel<<<(1536 * NC / 4 + 255) / 256, 256>>>(qkv_w, qkvwr, 1536 * NC / 4);
    round_kernel<<<(NC * NC / 4 + 255) / 256, 256>>>(out_w, outwr, NC * NC / 4);

    // 1. GroupNorm -> g_xn (rounded)
    groupnorm_kernel<<<NB * NG, 256>>>(x, norm_w, norm_b);

    // 2. QKV projection (rounded outputs)
    tf32mma_gemm<false, true><<<dim3(GN / 128, 1536 / 128, NB), 256>>>(
        qkvwr, xn, qkv_b, nullptr, qkvb, 1536);

    // 3. Flash attention (mma.sync) -> g_attn (rounded)
    attn_mma<<<dim3(8, NB * NH), 256, ATT_SMEM>>>(qkvb, attnb);

    // 4. Output projection + bias + skip -> d_out (NOT rounded)
    tf32mma_gemm<true, false><<<dim3(GN / 128, NC / 128, NB), 256>>>(
        outwr, attnb, out_b, x, out, NC);
}